// round 7
// baseline (speedup 1.0000x reference)
#include <cuda_runtime.h>

// TextEmbedding: gather [B,S,W,D] from table, per-token LayerNorm, sum over W.
// B=32, S=128, W=32, D=256  -> out [B*S, D] f32.
//
// R7: warp-per-position, 16 chunks x 2 words, 3-stage rotating load pipeline
// (prefetch distance 2 -> consume-issue gap ~2 process-chunks covers L2
// latency), <=85 regs for 3 CTAs/SM. Packed f32x2 math, fold warp reduction.

#define DIM 256
#define WORDS 32
#define EPS 1e-12f

typedef unsigned long long u64;

__device__ __forceinline__ u64 pack2(float lo, float hi) {
    u64 r; asm("mov.b64 %0, {%1, %2};" : "=l"(r) : "f"(lo), "f"(hi)); return r;
}
__device__ __forceinline__ void unpack2(u64 v, float& lo, float& hi) {
    asm("mov.b64 {%0, %1}, %2;" : "=f"(lo), "=f"(hi) : "l"(v));
}
__device__ __forceinline__ u64 add2(u64 a, u64 b) {
    u64 d; asm("add.rn.f32x2 %0, %1, %2;" : "=l"(d) : "l"(a), "l"(b)); return d;
}
__device__ __forceinline__ u64 mul2(u64 a, u64 b) {
    u64 d; asm("mul.rn.f32x2 %0, %1, %2;" : "=l"(d) : "l"(a), "l"(b)); return d;
}
__device__ __forceinline__ u64 fma2(u64 a, u64 b, u64 c) {
    u64 d; asm("fma.rn.f32x2 %0, %1, %2, %3;" : "=l"(d) : "l"(a), "l"(b), "l"(c)); return d;
}

// Load chunk c (words 2c, 2c+1): 4 coalesced LDG.128 (512B each).
__device__ __forceinline__ void load_chunk(const float* __restrict__ table,
                                           int id_lane, int c, int lane,
                                           float4 R[4]) {
    const int id0 = __shfl_sync(0xffffffffu, id_lane, 2 * c);
    const int id1 = __shfl_sync(0xffffffffu, id_lane, 2 * c + 1);
    const float4* row0 = (const float4*)(table + (size_t)id0 * DIM);
    const float4* row1 = (const float4*)(table + (size_t)id1 * DIM);
    R[0] = __ldg(row0 + lane);
    R[1] = __ldg(row0 + 32 + lane);
    R[2] = __ldg(row1 + lane);
    R[3] = __ldg(row1 + 32 + lane);
}

// Reduce 2 words in R: update acc[0..3] (f32x2 pairs) and mtot.
__device__ __forceinline__ void process_chunk(const float4 R[4], int lane,
                                              u64 acc[4], float& mtot) {
    // Per-lane partials: v = {s0, q0, s1, q1}
    float v[4];
    #pragma unroll
    for (int wi = 0; wi < 2; wi++) {
        const float4 ra = R[2 * wi], rb = R[2 * wi + 1];
        const u64 a01 = pack2(ra.x, ra.y);
        const u64 a23 = pack2(ra.z, ra.w);
        const u64 b01 = pack2(rb.x, rb.y);
        const u64 b23 = pack2(rb.z, rb.w);
        const u64 s2 = add2(add2(a01, a23), add2(b01, b23));
        const u64 q2 = fma2(a01, a01, fma2(a23, a23, fma2(b01, b01, mul2(b23, b23))));
        float sl, sh, ql, qh;
        unpack2(s2, sl, sh); unpack2(q2, ql, qh);
        v[2 * wi] = sl + sh; v[2 * wi + 1] = ql + qh;
    }

    // Fold across lane bit 16 (word select), bit 8 (s/q select); butterfly 4,2,1.
    const bool hi16 = (lane & 16) != 0;
    float w2[2];
    #pragma unroll
    for (int j = 0; j < 2; j++) {
        float send = hi16 ? v[j] : v[j + 2];
        float keep = hi16 ? v[j + 2] : v[j];
        w2[j] = keep + __shfl_xor_sync(0xffffffffu, send, 16);
    }
    const bool hi8 = (lane & 8) != 0;
    float y;
    {
        float send = hi8 ? w2[0] : w2[1];
        float keep = hi8 ? w2[1] : w2[0];
        y = keep + __shfl_xor_sync(0xffffffffu, send, 8);
    }
    y += __shfl_xor_sync(0xffffffffu, y, 4);
    y += __shfl_xor_sync(0xffffffffu, y, 2);
    y += __shfl_xor_sync(0xffffffffu, y, 1);
    // Lane holds: word W = b16; b8 = 0 -> s_W, b8 = 1 -> q_W.

    const float p  = __shfl_xor_sync(0xffffffffu, y, 8);
    const float s_ = hi8 ? p : y;
    const float q_ = hi8 ? y : p;
    const float mu  = s_ * (1.0f / 256.0f);
    const float var = q_ * (1.0f / 256.0f) - mu * mu;
    const float r_  = rsqrtf(var + EPS);
    const float msh = -mu * r_;

    // Chunk shift total over its 2 words.
    mtot += msh + __shfl_xor_sync(0xffffffffu, msh, 16);

    // rstd for word0 (lane 0) and word1 (lane 16); packed accumulate.
    const float r0 = __shfl_sync(0xffffffffu, r_, 0);
    const float r1 = __shfl_sync(0xffffffffu, r_, 16);
    const u64 rr0 = pack2(r0, r0);
    const u64 rr1 = pack2(r1, r1);
    acc[0] = fma2(pack2(R[0].x, R[0].y), rr0, acc[0]);
    acc[1] = fma2(pack2(R[0].z, R[0].w), rr0, acc[1]);
    acc[2] = fma2(pack2(R[1].x, R[1].y), rr0, acc[2]);
    acc[3] = fma2(pack2(R[1].z, R[1].w), rr0, acc[3]);
    acc[0] = fma2(pack2(R[2].x, R[2].y), rr1, acc[0]);
    acc[1] = fma2(pack2(R[2].z, R[2].w), rr1, acc[1]);
    acc[2] = fma2(pack2(R[3].x, R[3].y), rr1, acc[2]);
    acc[3] = fma2(pack2(R[3].z, R[3].w), rr1, acc[3]);
}

__global__ __launch_bounds__(256, 3)
void emb_ln_sum_kernel(const int* __restrict__ ids,
                       const float* __restrict__ table,
                       const float* __restrict__ gamma,
                       const float* __restrict__ beta,
                       float* __restrict__ out) {
    const int tid  = threadIdx.x;
    const int warp = tid >> 5;
    const int lane = tid & 31;
    const int pos  = blockIdx.x * 8 + warp;   // 0..4095

    // Lane L holds id of word L for this position (one coalesced LDG.32).
    const int id_lane = __ldg(ids + pos * WORDS + lane);

    u64 acc[4];
    const u64 z = pack2(0.0f, 0.0f);
    acc[0] = z; acc[1] = z; acc[2] = z; acc[3] = z;
    float mtot = 0.0f;

    // 3-stage rotating pipeline over 16 chunks (prefetch distance 2).
    float4 B0[4], B1[4], B2[4];
    load_chunk(table, id_lane, 0, lane, B0);
    load_chunk(table, id_lane, 1, lane, B1);

    #pragma unroll
    for (int c = 0; c < 16; c++) {
        float4* cur  = (c % 3 == 0) ? B0 : (c % 3 == 1) ? B1 : B2;
        float4* next = ((c + 2) % 3 == 0) ? B0 : ((c + 2) % 3 == 1) ? B1 : B2;
        if (c + 2 < 16) load_chunk(table, id_lane, c + 2, lane, next);
        process_chunk(cur, lane, acc, mtot);
    }

    // out = (acc + mtot) * gamma + 32 * beta, per lane dims.
    float a0, a1, a2, a3, a4, a5, a6, a7;
    unpack2(acc[0], a0, a1); unpack2(acc[1], a2, a3);
    unpack2(acc[2], a4, a5); unpack2(acc[3], a6, a7);

    const float4 g0  = __ldg((const float4*)gamma + lane);
    const float4 g1  = __ldg((const float4*)gamma + 32 + lane);
    const float4 bt0 = __ldg((const float4*)beta + lane);
    const float4 bt1 = __ldg((const float4*)beta + 32 + lane);

    float4 o0, o1;
    o0.x = fmaf(a0 + mtot, g0.x, 32.0f * bt0.x);
    o0.y = fmaf(a1 + mtot, g0.y, 32.0f * bt0.y);
    o0.z = fmaf(a2 + mtot, g0.z, 32.0f * bt0.z);
    o0.w = fmaf(a3 + mtot, g0.w, 32.0f * bt0.w);
    o1.x = fmaf(a4 + mtot, g1.x, 32.0f * bt1.x);
    o1.y = fmaf(a5 + mtot, g1.y, 32.0f * bt1.y);
    o1.z = fmaf(a6 + mtot, g1.z, 32.0f * bt1.z);
    o1.w = fmaf(a7 + mtot, g1.w, 32.0f * bt1.w);

    float4* op = (float4*)(out + (size_t)pos * DIM);
    op[lane]      = o0;   // dims [4*lane, 4*lane+4)
    op[32 + lane] = o1;   // dims [128+4*lane, ...)
}

extern "C" void kernel_launch(void* const* d_in, const int* in_sizes, int n_in,
                              void* d_out, int out_size) {
    const int*   ids   = (const int*)d_in[0];     // [32,128,32] int32
    const float* table = (const float*)d_in[1];   // [32000,256] f32
    const float* gamma = (const float*)d_in[2];   // [256]
    const float* beta  = (const float*)d_in[3];   // [256]
    float* out = (float*)d_out;                   // [32,128,256] f32

    const int n_pos = in_sizes[0] / WORDS;        // 4096
    emb_ln_sum_kernel<<<n_pos / 8, 256>>>(ids, table, gamma, beta, out);
}

// round 8
// speedup vs baseline: 1.1379x; 1.1379x over previous
#include <cuda_runtime.h>
#include <cstdint>

// TextEmbedding: gather [B,S,W,D] from table, per-token LayerNorm, sum over W.
// B=32, S=128, W=32, D=256  -> out [B*S, D] f32.
//
// R8: warp-per-position; cp.async.cg (LDGSTS) pipeline into a 3-stage smem
// ring (2 words/chunk, prefetch distance 2). In-flight data lives in smem,
// not registers -> ~56 regs, 4 CTAs/SM, sustained 8 LDGSTS.128 in flight per
// warp. Each lane copies and reads only its own bytes -> no barriers; the
// shfl.sync reduction provides all cross-lane ordering. .cg bypasses L1
// (random gather has no reuse).

#define DIM 256
#define WORDS 32
#define EPS 1e-12f
#define STAGES 3
#define NCHUNK 16           // 2 words per chunk

typedef unsigned long long u64;

__device__ __forceinline__ u64 pack2(float lo, float hi) {
    u64 r; asm("mov.b64 %0, {%1, %2};" : "=l"(r) : "f"(lo), "f"(hi)); return r;
}
__device__ __forceinline__ void unpack2(u64 v, float& lo, float& hi) {
    asm("mov.b64 {%0, %1}, %2;" : "=f"(lo), "=f"(hi) : "l"(v));
}
__device__ __forceinline__ u64 add2(u64 a, u64 b) {
    u64 d; asm("add.rn.f32x2 %0, %1, %2;" : "=l"(d) : "l"(a), "l"(b)); return d;
}
__device__ __forceinline__ u64 mul2(u64 a, u64 b) {
    u64 d; asm("mul.rn.f32x2 %0, %1, %2;" : "=l"(d) : "l"(a), "l"(b)); return d;
}
__device__ __forceinline__ u64 fma2(u64 a, u64 b, u64 c) {
    u64 d; asm("fma.rn.f32x2 %0, %1, %2, %3;" : "=l"(d) : "l"(a), "l"(b), "l"(c)); return d;
}

__device__ __forceinline__ void cp16(uint32_t dst_smem, const void* src) {
    asm volatile("cp.async.cg.shared.global [%0], [%1], 16;"
                 :: "r"(dst_smem), "l"(src));
}
__device__ __forceinline__ void cp_commit() {
    asm volatile("cp.async.commit_group;");
}
template <int N> __device__ __forceinline__ void cp_wait() {
    asm volatile("cp.async.wait_group %0;" :: "n"(N));
}

__global__ __launch_bounds__(256, 4)
void emb_ln_sum_kernel(const int* __restrict__ ids,
                       const float* __restrict__ table,
                       const float* __restrict__ gamma,
                       const float* __restrict__ beta,
                       float* __restrict__ out) {
    // [warp][stage][slot][lane] : slot = {w0.lo, w0.hi, w1.lo, w1.hi}
    __shared__ float4 buf[8][STAGES][4][32];

    const int tid  = threadIdx.x;
    const int warp = tid >> 5;
    const int lane = tid & 31;
    const int pos  = blockIdx.x * 8 + warp;   // 0..4095

    // Lane L holds id of word L (one coalesced LDG.32 per warp).
    const int id_lane = __ldg(ids + pos * WORDS + lane);

    // Base smem address (32-bit shared window) for this warp/lane.
    const uint32_t sbase =
        (uint32_t)__cvta_generic_to_shared(&buf[warp][0][0][lane]);
    const uint32_t stage_stride = 4 * 32 * sizeof(float4);  // 2048 B
    const uint32_t slot_stride  = 32 * sizeof(float4);      // 512 B

    // Producer: issue chunk c (words 2c, 2c+1) -> stage c%STAGES.
    auto issue = [&](int c) {
        const int id0 = __shfl_sync(0xffffffffu, id_lane, 2 * c);
        const int id1 = __shfl_sync(0xffffffffu, id_lane, 2 * c + 1);
        const float* r0 = table + (size_t)id0 * DIM + 4 * lane;
        const float* r1 = table + (size_t)id1 * DIM + 4 * lane;
        const uint32_t s = sbase + (uint32_t)(c % STAGES) * stage_stride;
        cp16(s,                   r0);
        cp16(s + slot_stride,     r0 + 128);
        cp16(s + 2 * slot_stride, r1);
        cp16(s + 3 * slot_stride, r1 + 128);
        cp_commit();
    };

    u64 acc[4];
    const u64 z = pack2(0.0f, 0.0f);
    acc[0] = z; acc[1] = z; acc[2] = z; acc[3] = z;
    float mtot = 0.0f;

    issue(0);
    issue(1);

    #pragma unroll
    for (int c = 0; c < NCHUNK; c++) {
        if (c + 2 < NCHUNK) issue(c + 2);

        // Wait until chunk c's group has landed.
        if (c + 2 < NCHUNK)      cp_wait<2>();
        else if (c + 1 < NCHUNK) cp_wait<1>();
        else                     cp_wait<0>();

        // Read this lane's own bytes back from smem.
        const float4* sp = &buf[warp][c % STAGES][0][lane];
        const float4 R0 = sp[0];
        const float4 R1 = sp[32];
        const float4 R2 = sp[64];
        const float4 R3 = sp[96];

        // Per-lane partials: v = {s0, q0, s1, q1}
        float v[4];
        {
            const u64 a01 = pack2(R0.x, R0.y), a23 = pack2(R0.z, R0.w);
            const u64 b01 = pack2(R1.x, R1.y), b23 = pack2(R1.z, R1.w);
            const u64 s2 = add2(add2(a01, a23), add2(b01, b23));
            const u64 q2 = fma2(a01, a01, fma2(a23, a23, fma2(b01, b01, mul2(b23, b23))));
            float sl, sh, ql, qh;
            unpack2(s2, sl, sh); unpack2(q2, ql, qh);
            v[0] = sl + sh; v[1] = ql + qh;
        }
        {
            const u64 a01 = pack2(R2.x, R2.y), a23 = pack2(R2.z, R2.w);
            const u64 b01 = pack2(R3.x, R3.y), b23 = pack2(R3.z, R3.w);
            const u64 s2 = add2(add2(a01, a23), add2(b01, b23));
            const u64 q2 = fma2(a01, a01, fma2(a23, a23, fma2(b01, b01, mul2(b23, b23))));
            float sl, sh, ql, qh;
            unpack2(s2, sl, sh); unpack2(q2, ql, qh);
            v[2] = sl + sh; v[3] = ql + qh;
        }

        // Fold: bit16 selects word, bit8 selects s/q; butterfly 4,2,1.
        const bool hi16 = (lane & 16) != 0;
        float w2[2];
        #pragma unroll
        for (int j = 0; j < 2; j++) {
            float send = hi16 ? v[j] : v[j + 2];
            float keep = hi16 ? v[j + 2] : v[j];
            w2[j] = keep + __shfl_xor_sync(0xffffffffu, send, 16);
        }
        const bool hi8 = (lane & 8) != 0;
        float y;
        {
            float send = hi8 ? w2[0] : w2[1];
            float keep = hi8 ? w2[1] : w2[0];
            y = keep + __shfl_xor_sync(0xffffffffu, send, 8);
        }
        y += __shfl_xor_sync(0xffffffffu, y, 4);
        y += __shfl_xor_sync(0xffffffffu, y, 2);
        y += __shfl_xor_sync(0xffffffffu, y, 1);
        // Lane holds: word W = b16; b8 = 0 -> s_W, b8 = 1 -> q_W.

        const float p  = __shfl_xor_sync(0xffffffffu, y, 8);
        const float s_ = hi8 ? p : y;
        const float q_ = hi8 ? y : p;
        const float mu  = s_ * (1.0f / 256.0f);
        const float var = q_ * (1.0f / 256.0f) - mu * mu;
        const float r_  = rsqrtf(var + EPS);
        const float msh = -mu * r_;

        mtot += msh + __shfl_xor_sync(0xffffffffu, msh, 16);

        const float r0 = __shfl_sync(0xffffffffu, r_, 0);
        const float r1 = __shfl_sync(0xffffffffu, r_, 16);
        const u64 rr0 = pack2(r0, r0);
        const u64 rr1 = pack2(r1, r1);
        acc[0] = fma2(pack2(R0.x, R0.y), rr0, acc[0]);
        acc[1] = fma2(pack2(R0.z, R0.w), rr0, acc[1]);
        acc[2] = fma2(pack2(R1.x, R1.y), rr0, acc[2]);
        acc[3] = fma2(pack2(R1.z, R1.w), rr0, acc[3]);
        acc[0] = fma2(pack2(R2.x, R2.y), rr1, acc[0]);
        acc[1] = fma2(pack2(R2.z, R2.w), rr1, acc[1]);
        acc[2] = fma2(pack2(R3.x, R3.y), rr1, acc[2]);
        acc[3] = fma2(pack2(R3.z, R3.w), rr1, acc[3]);
    }

    // out = (acc + mtot) * gamma + 32 * beta, per lane dims.
    float a0, a1, a2, a3, a4, a5, a6, a7;
    unpack2(acc[0], a0, a1); unpack2(acc[1], a2, a3);
    unpack2(acc[2], a4, a5); unpack2(acc[3], a6, a7);

    const float4 g0  = __ldg((const float4*)gamma + lane);
    const float4 g1  = __ldg((const float4*)gamma + 32 + lane);
    const float4 bt0 = __ldg((const float4*)beta + lane);
    const float4 bt1 = __ldg((const float4*)beta + 32 + lane);

    float4 o0, o1;
    o0.x = fmaf(a0 + mtot, g0.x, 32.0f * bt0.x);
    o0.y = fmaf(a1 + mtot, g0.y, 32.0f * bt0.y);
    o0.z = fmaf(a2 + mtot, g0.z, 32.0f * bt0.z);
    o0.w = fmaf(a3 + mtot, g0.w, 32.0f * bt0.w);
    o1.x = fmaf(a4 + mtot, g1.x, 32.0f * bt1.x);
    o1.y = fmaf(a5 + mtot, g1.y, 32.0f * bt1.y);
    o1.z = fmaf(a6 + mtot, g1.z, 32.0f * bt1.z);
    o1.w = fmaf(a7 + mtot, g1.w, 32.0f * bt1.w);

    float4* op = (float4*)(out + (size_t)pos * DIM);
    op[lane]      = o0;   // dims [4*lane, 4*lane+4)
    op[32 + lane] = o1;   // dims [128+4*lane, ...)
}

extern "C" void kernel_launch(void* const* d_in, const int* in_sizes, int n_in,
                              void* d_out, int out_size) {
    const int*   ids   = (const int*)d_in[0];     // [32,128,32] int32
    const float* table = (const float*)d_in[1];   // [32000,256] f32
    const float* gamma = (const float*)d_in[2];   // [256]
    const float* beta  = (const float*)d_in[3];   // [256]
    float* out = (float*)d_out;                   // [32,128,256] f32

    const int n_pos = in_sizes[0] / WORDS;        // 4096
    emb_ln_sum_kernel<<<n_pos / 8, 256>>>(ids, table, gamma, beta, out);
}